// round 1
// baseline (speedup 1.0000x reference)
#include <cuda_runtime.h>
#include <math.h>

#define N_RESV 384
#define CSV    384
#define CZV    128
#define NHV    12
#define CHV    16
#define NQPV   4
#define NPVV   8
#define DPROJ  1152   // 192*3 + 144*2 + 288
#define DCAT   2112   // 192 + 288 + 96 + 1536

// ---------------- scratch (device globals; no allocation allowed) ------------
__device__ float g_Wcat[CSV * DPROJ];
__device__ float g_bcat[DPROJ];
__device__ float g_raw [N_RESV * DPROJ];
__device__ float g_q [NHV * N_RESV * CHV];
__device__ float g_k [NHV * N_RESV * CHV];
__device__ float g_v [NHV * N_RESV * CHV];
__device__ float g_tqp[NHV * NQPV * N_RESV * 3];
__device__ float g_tkp[NHV * NQPV * N_RESV * 3];
__device__ float g_tvp[NHV * NPVV * N_RESV * 3];
__device__ float g_bias[NHV * N_RESV * N_RESV];
__device__ float g_att [NHV * N_RESV * N_RESV];
__device__ float g_concat[N_RESV * DCAT];

// ---------------- kernel 1: build concatenated projection weights ------------
__global__ void build_wcat_kernel(
    const float* Wq, const float* bq, const float* Wk, const float* bk,
    const float* Wv, const float* bv, const float* Wqp, const float* bqp,
    const float* Wkp, const float* bkp, const float* Wvp, const float* bvp)
{
    int idx = blockIdx.x * blockDim.x + threadIdx.x;
    int stride = gridDim.x * blockDim.x;
    const int total = CSV * DPROJ;
    for (int t = idx; t < total; t += stride) {
        int c = t / DPROJ, d = t % DPROJ;
        float v;
        if      (d < 192)  v = Wq [c * 192 + d];
        else if (d < 384)  v = Wk [c * 192 + (d - 192)];
        else if (d < 576)  v = Wv [c * 192 + (d - 384)];
        else if (d < 720)  v = Wqp[c * 144 + (d - 576)];
        else if (d < 864)  v = Wkp[c * 144 + (d - 720)];
        else               v = Wvp[c * 288 + (d - 864)];
        g_Wcat[t] = v;
    }
    for (int d = idx; d < DPROJ; d += stride) {
        float v;
        if      (d < 192)  v = bq [d];
        else if (d < 384)  v = bk [d - 192];
        else if (d < 576)  v = bv [d - 384];
        else if (d < 720)  v = bqp[d - 576];
        else if (d < 864)  v = bkp[d - 720];
        else               v = bvp[d - 864];
        g_bcat[d] = v;
    }
}

// ---------------- generic tiled GEMM: C[M,N] = A[M,K] @ W[K,N] + bias --------
// grid = (M/32, N/64), block = 256. M%32==0, N%64==0, K%32==0 assumed.
__global__ void gemm_tiled_kernel(const float* __restrict__ A, int lda,
                                  const float* __restrict__ W, int ldw,
                                  const float* __restrict__ bias,
                                  float* __restrict__ C, int ldc, int K)
{
    __shared__ float sA[32][32];
    __shared__ float sW[32][64];
    int i0 = blockIdx.x * 32;
    int o0 = blockIdx.y * 64;
    int ol = threadIdx.x & 63;   // 0..63
    int ig = threadIdx.x >> 6;   // 0..3
    float acc[8];
#pragma unroll
    for (int r = 0; r < 8; r++) acc[r] = 0.f;

    for (int d0 = 0; d0 < K; d0 += 32) {
        __syncthreads();
        for (int idx = threadIdx.x; idx < 32 * 32; idx += 256) {
            int r = idx >> 5, cc = idx & 31;
            sA[r][cc] = A[(size_t)(i0 + r) * lda + d0 + cc];
        }
        for (int idx = threadIdx.x; idx < 32 * 64; idx += 256) {
            int r = idx >> 6, cc = idx & 63;
            sW[r][cc] = W[(size_t)(d0 + r) * ldw + o0 + cc];
        }
        __syncthreads();
#pragma unroll
        for (int dd = 0; dd < 32; dd++) {
            float w = sW[dd][ol];
#pragma unroll
            for (int r = 0; r < 8; r++)
                acc[r] = fmaf(sA[ig + r * 4][dd], w, acc[r]);
        }
    }
    float bv = bias[o0 + ol];
#pragma unroll
    for (int r = 0; r < 8; r++)
        C[(size_t)(i0 + ig + r * 4) * ldc + o0 + ol] = acc[r] + bv;
}

// ---------------- kernel 3: scatter projections + transform points -----------
__global__ void scatter_kernel(const float* __restrict__ T)
{
    int i = blockIdx.x;
    const float* raw = g_raw + (size_t)i * DPROJ;
    const float* Ti  = T + (size_t)i * 16;

    for (int t = threadIdx.x; t < 768; t += blockDim.x) {
        if (t < 576) {
            int kind = t / 192, d = t % 192;
            int h = d / 16, c = d % 16;
            float v = raw[kind * 192 + d];
            if (kind == 0) v *= 0.25f;  // q * 1/sqrt(C)
            float* dst = (kind == 0) ? g_q : ((kind == 1) ? g_k : g_v);
            dst[(h * N_RESV + i) * CHV + c] = v;
        } else {
            int t2 = t - 576;
            int kind, hp, P, base;
            if      (t2 < 48)  { kind = 0; hp = t2;       P = NQPV; base = 576; }
            else if (t2 < 96)  { kind = 1; hp = t2 - 48;  P = NQPV; base = 720; }
            else               { kind = 2; hp = t2 - 96;  P = NPVV; base = 864; }
            int HP = NHV * P;
            float px = raw[base + 0 * HP + hp];
            float py = raw[base + 1 * HP + hp];
            float pz = raw[base + 2 * HP + hp];
            float ox = Ti[0] * px + Ti[1] * py + Ti[2]  * pz + Ti[3];
            float oy = Ti[4] * px + Ti[5] * py + Ti[6]  * pz + Ti[7];
            float oz = Ti[8] * px + Ti[9] * py + Ti[10] * pz + Ti[11];
            float* dst = (kind == 0) ? g_tqp : ((kind == 1) ? g_tkp : g_tvp);
            float* o = dst + ((size_t)hp * N_RESV + i) * 3;  // hp = h*P+p
            o[0] = ox; o[1] = oy; o[2] = oz;
        }
    }
}

// ---------------- kernel 4: bias[h,i,j] = z[i,j,:] @ Wb[:,h] + bb[h] ---------
// warp per (i,j); block = 128 threads = 4 warps.
__global__ void bias_kernel(const float* __restrict__ z,
                            const float* __restrict__ Wb,
                            const float* __restrict__ bb)
{
    __shared__ float sWb[CZV * NHV];
    for (int t = threadIdx.x; t < CZV * NHV; t += blockDim.x) sWb[t] = Wb[t];
    __syncthreads();

    int gw   = blockIdx.x * (blockDim.x >> 5) + (threadIdx.x >> 5);
    int lane = threadIdx.x & 31;
    int i = gw / N_RESV, j = gw % N_RESV;

    const float4 zv = ((const float4*)(z + ((size_t)i * N_RESV + j) * CZV))[lane];
    int c = lane * 4;
    float acc[NHV];
#pragma unroll
    for (int h = 0; h < NHV; h++) {
        acc[h] = zv.x * sWb[(c + 0) * NHV + h]
               + zv.y * sWb[(c + 1) * NHV + h]
               + zv.z * sWb[(c + 2) * NHV + h]
               + zv.w * sWb[(c + 3) * NHV + h];
    }
#pragma unroll
    for (int off = 16; off; off >>= 1)
#pragma unroll
        for (int h = 0; h < NHV; h++)
            acc[h] += __shfl_xor_sync(0xffffffffu, acc[h], off);
    if (lane < NHV)
        g_bias[((size_t)lane * N_RESV + i) * N_RESV + j] = acc[lane] + bb[lane];
}

// ---------------- kernel 5: logits + softmax per (h, i) ----------------------
// grid = (384, 12), block = 128
__global__ void att_kernel(const float* __restrict__ head_weights)
{
    int i = blockIdx.x, h = blockIdx.y;
    __shared__ float sq[CHV];
    __shared__ float sp[NQPV * 3];
    __shared__ float slog[N_RESV];
    __shared__ float red_m[4];
    __shared__ float red_s[4];

    if (threadIdx.x < CHV) sq[threadIdx.x] = g_q[(h * N_RESV + i) * CHV + threadIdx.x];
    if (threadIdx.x < NQPV * 3) {
        int p = threadIdx.x / 3, d = threadIdx.x % 3;
        sp[threadIdx.x] = g_tqp[((h * NQPV + p) * N_RESV + i) * 3 + d];
    }
    float hw = head_weights[h];
    float gamma = (hw > 20.f) ? hw : log1pf(expf(hw));
    const float wc = 0.23570226039551584f;   // sqrt(2/(9*4))
    const float wl = 0.57735026918962576f;   // sqrt(1/3)
    float coef = gamma * wc * 0.5f;
    __syncthreads();

    const float* brow = &g_bias[((size_t)h * N_RESV + i) * N_RESV];
    float lmax = -1e30f;
    for (int j = threadIdx.x; j < N_RESV; j += blockDim.x) {
        const float* kj = &g_k[(h * N_RESV + j) * CHV];
        float qk = 0.f;
#pragma unroll
        for (int c = 0; c < CHV; c++) qk = fmaf(sq[c], kj[c], qk);
        float d2 = 0.f;
#pragma unroll
        for (int p = 0; p < NQPV; p++) {
            const float* kp = &g_tkp[((h * NQPV + p) * N_RESV + j) * 3];
            float dx = sp[p * 3 + 0] - kp[0];
            float dy = sp[p * 3 + 1] - kp[1];
            float dz = sp[p * 3 + 2] - kp[2];
            d2 += dx * dx + dy * dy + dz * dz;
        }
        float lg = wl * (qk + brow[j] - coef * d2);
        slog[j] = lg;
        lmax = fmaxf(lmax, lg);
    }
    // block max
    float v = lmax;
#pragma unroll
    for (int o = 16; o; o >>= 1) v = fmaxf(v, __shfl_xor_sync(0xffffffffu, v, o));
    if ((threadIdx.x & 31) == 0) red_m[threadIdx.x >> 5] = v;
    __syncthreads();
    float m = fmaxf(fmaxf(red_m[0], red_m[1]), fmaxf(red_m[2], red_m[3]));

    float lsum = 0.f;
    for (int j = threadIdx.x; j < N_RESV; j += blockDim.x) {
        float e = expf(slog[j] - m);
        slog[j] = e;
        lsum += e;
    }
    v = lsum;
#pragma unroll
    for (int o = 16; o; o >>= 1) v += __shfl_xor_sync(0xffffffffu, v, o);
    if ((threadIdx.x & 31) == 0) red_s[threadIdx.x >> 5] = v;
    __syncthreads();
    float inv = 1.f / (red_s[0] + red_s[1] + red_s[2] + red_s[3]);

    float* arow = &g_att[((size_t)h * N_RESV + i) * N_RESV];
    for (int j = threadIdx.x; j < N_RESV; j += blockDim.x)
        arow[j] = slog[j] * inv;
}

// ---------------- kernel 6: per-residue outputs -> concat row ----------------
// block per i, 256 threads
__global__ void out_kernel(const float* __restrict__ z,
                           const float* __restrict__ T)
{
    int i = blockIdx.x;
    __shared__ float att[NHV][N_RESV];     // 18 KB
    __shared__ float ztile[32][CZV];       // 16 KB
    __shared__ float vatt[NHV * NPVV * 3]; // 288

    for (int t = threadIdx.x; t < NHV * N_RESV; t += blockDim.x) {
        int h = t / N_RESV, j = t % N_RESV;
        att[h][j] = g_att[((size_t)h * N_RESV + i) * N_RESV + j];
    }
    __syncthreads();

    float* crow = g_concat + (size_t)i * DCAT;

    // pairwise: 12 heads x 128 c; thread: c = tid&127, head-group = tid>>7 (6 heads each)
    int c  = threadIdx.x & 127;
    int hg = threadIdx.x >> 7;
    float acc[6];
#pragma unroll
    for (int k = 0; k < 6; k++) acc[k] = 0.f;

    for (int j0 = 0; j0 < N_RESV; j0 += 32) {
        __syncthreads();
        const float4* zsrc = (const float4*)(z + ((size_t)i * N_RESV + j0) * CZV);
        float4* zdst = (float4*)&ztile[0][0];
        for (int idx = threadIdx.x; idx < 32 * CZV / 4; idx += 256) zdst[idx] = zsrc[idx];
        __syncthreads();
#pragma unroll 8
        for (int jj = 0; jj < 32; jj++) {
            float zv = ztile[jj][c];
#pragma unroll
            for (int k = 0; k < 6; k++)
                acc[k] = fmaf(att[hg * 6 + k][j0 + jj], zv, acc[k]);
        }
    }
#pragma unroll
    for (int k = 0; k < 6; k++)
        crow[576 + (hg * 6 + k) * CZV + c] = acc[k];

    __syncthreads();

    // v_out (192 tasks) and v_att (288 tasks)
    for (int t = threadIdx.x; t < 480; t += 256) {
        if (t < 192) {
            int h = t / 16, cc = t % 16;
            float a = 0.f;
            for (int j = 0; j < N_RESV; j++)
                a = fmaf(att[h][j], g_v[(h * N_RESV + j) * CHV + cc], a);
            crow[h * 16 + cc] = a;
        } else {
            int u = t - 192;
            int h = u / 24, r = u % 24, p = r / 3, d = r % 3;
            float a = 0.f;
            for (int j = 0; j < N_RESV; j++)
                a = fmaf(att[h][j], g_tvp[((h * NPVV + p) * N_RESV + j) * 3 + d], a);
            vatt[u] = a;   // u = h*24 + p*3 + d
        }
    }
    __syncthreads();

    // inverse transform + norm: 96 tasks (h,p)
    const float* Ti = T + (size_t)i * 16;
    for (int t = threadIdx.x; t < 96; t += 256) {
        int h = t / 8, p = t % 8;
        float px = vatt[h * 24 + p * 3 + 0] - Ti[3];
        float py = vatt[h * 24 + p * 3 + 1] - Ti[7];
        float pz = vatt[h * 24 + p * 3 + 2] - Ti[11];
        float ox = Ti[0] * px + Ti[4] * py + Ti[8]  * pz;
        float oy = Ti[1] * px + Ti[5] * py + Ti[9]  * pz;
        float oz = Ti[2] * px + Ti[6] * py + Ti[10] * pz;
        crow[192 +   0 + h * 8 + p] = ox;
        crow[192 +  96 + h * 8 + p] = oy;
        crow[192 + 192 + h * 8 + p] = oz;
        crow[480 + h * 8 + p] = sqrtf(ox * ox + oy * oy + oz * oz);
    }
}

// ---------------- launch ------------------------------------------------------
extern "C" void kernel_launch(void* const* d_in, const int* in_sizes, int n_in,
                              void* d_out, int out_size)
{
    const float* s   = (const float*)d_in[0];
    const float* z   = (const float*)d_in[1];
    const float* T   = (const float*)d_in[2];
    const float* Wq  = (const float*)d_in[3];
    const float* bq  = (const float*)d_in[4];
    const float* Wk  = (const float*)d_in[5];
    const float* bk  = (const float*)d_in[6];
    const float* Wv  = (const float*)d_in[7];
    const float* bv  = (const float*)d_in[8];
    const float* Wqp = (const float*)d_in[9];
    const float* bqp = (const float*)d_in[10];
    const float* Wkp = (const float*)d_in[11];
    const float* bkp = (const float*)d_in[12];
    const float* Wvp = (const float*)d_in[13];
    const float* bvp = (const float*)d_in[14];
    const float* Wb  = (const float*)d_in[15];
    const float* bb  = (const float*)d_in[16];
    const float* Wo  = (const float*)d_in[17];
    const float* bo  = (const float*)d_in[18];
    const float* hwt = (const float*)d_in[19];

    float* out = (float*)d_out;

    float* raw_p;    cudaGetSymbolAddress((void**)&raw_p,    g_raw);
    float* wcat_p;   cudaGetSymbolAddress((void**)&wcat_p,   g_Wcat);
    float* bcat_p;   cudaGetSymbolAddress((void**)&bcat_p,   g_bcat);
    float* concat_p; cudaGetSymbolAddress((void**)&concat_p, g_concat);

    build_wcat_kernel<<<432, 256>>>(Wq, bq, Wk, bk, Wv, bv,
                                    Wqp, bqp, Wkp, bkp, Wvp, bvp);

    // projections: (384 x 384) @ (384 x 1152)
    gemm_tiled_kernel<<<dim3(N_RESV / 32, DPROJ / 64), 256>>>(
        s, CSV, wcat_p, DPROJ, bcat_p, raw_p, DPROJ, CSV);

    scatter_kernel<<<N_RESV, 256>>>(T);

    bias_kernel<<<(N_RESV * N_RESV) / 4, 128>>>(z, Wb, bb);

    att_kernel<<<dim3(N_RESV, NHV), 128>>>(hwt);

    out_kernel<<<N_RESV, 256>>>(z, T);

    // final: (384 x 2112) @ (2112 x 384)
    gemm_tiled_kernel<<<dim3(N_RESV / 32, N_RESV / 64), 256>>>(
        concat_p, DCAT, Wo, CSV, bo, out, CSV, DCAT);
}

// round 2
// speedup vs baseline: 1.5015x; 1.5015x over previous
#include <cuda_runtime.h>
#include <math.h>

#define N_RESV 384
#define CSV    384
#define CZV    128
#define NHV    12
#define CHV    16
#define NQPV   4
#define NPVV   8
#define DPROJ  1152   // 192*3 + 144*2 + 288
#define DCAT   2112   // 192 + 288 + 96 + 1536
#define NROWS  (N_RESV * N_RESV)   // 147456

// ---------------- scratch ----------------------------------------------------
__device__ float g_Wcat[CSV * DPROJ];
__device__ float g_bcat[DPROJ];
__device__ float g_raw [N_RESV * DPROJ];
__device__ float g_q [NHV * N_RESV * CHV];
__device__ float g_k [NHV * N_RESV * CHV];
__device__ float g_v [NHV * N_RESV * CHV];
__device__ float g_tqp[NHV * NQPV * N_RESV * 3];
__device__ float g_tkp[NHV * NQPV * N_RESV * 3];
__device__ float g_tvp[NHV * NPVV * N_RESV * 3];
__device__ float g_bias[NHV * NROWS];
__device__ float g_att [NHV * NROWS];
__device__ float g_av  [NHV * N_RESV * 40];   // per (h,i): 16 v_out | 24 v_att
__device__ float g_concat[N_RESV * DCAT];

// ---------------- kernel 1: build concatenated projection weights ------------
__global__ void build_wcat_kernel(
    const float* Wq, const float* bq, const float* Wk, const float* bk,
    const float* Wv, const float* bv, const float* Wqp, const float* bqp,
    const float* Wkp, const float* bkp, const float* Wvp, const float* bvp)
{
    int idx = blockIdx.x * blockDim.x + threadIdx.x;
    int stride = gridDim.x * blockDim.x;
    const int total = CSV * DPROJ;
    for (int t = idx; t < total; t += stride) {
        int c = t / DPROJ, d = t % DPROJ;
        float v;
        if      (d < 192)  v = Wq [c * 192 + d];
        else if (d < 384)  v = Wk [c * 192 + (d - 192)];
        else if (d < 576)  v = Wv [c * 192 + (d - 384)];
        else if (d < 720)  v = Wqp[c * 144 + (d - 576)];
        else if (d < 864)  v = Wkp[c * 144 + (d - 720)];
        else               v = Wvp[c * 288 + (d - 864)];
        g_Wcat[t] = v;
    }
    for (int d = idx; d < DPROJ; d += stride) {
        float v;
        if      (d < 192)  v = bq [d];
        else if (d < 384)  v = bk [d - 192];
        else if (d < 576)  v = bv [d - 384];
        else if (d < 720)  v = bqp[d - 576];
        else if (d < 864)  v = bkp[d - 720];
        else               v = bvp[d - 864];
        g_bcat[d] = v;
    }
}

// ---------------- generic tiled GEMM: C[M,N] = A[M,K] @ W[K,N] + bias --------
__global__ void gemm_tiled_kernel(const float* __restrict__ A, int lda,
                                  const float* __restrict__ W, int ldw,
                                  const float* __restrict__ bias,
                                  float* __restrict__ C, int ldc, int K)
{
    __shared__ float sA[32][32];
    __shared__ float sW[32][64];
    int i0 = blockIdx.x * 32;
    int o0 = blockIdx.y * 64;
    int ol = threadIdx.x & 63;
    int ig = threadIdx.x >> 6;
    float acc[8];
#pragma unroll
    for (int r = 0; r < 8; r++) acc[r] = 0.f;

    for (int d0 = 0; d0 < K; d0 += 32) {
        __syncthreads();
        for (int idx = threadIdx.x; idx < 32 * 32; idx += 256) {
            int r = idx >> 5, cc = idx & 31;
            sA[r][cc] = A[(size_t)(i0 + r) * lda + d0 + cc];
        }
        for (int idx = threadIdx.x; idx < 32 * 64; idx += 256) {
            int r = idx >> 6, cc = idx & 63;
            sW[r][cc] = W[(size_t)(d0 + r) * ldw + o0 + cc];
        }
        __syncthreads();
#pragma unroll
        for (int dd = 0; dd < 32; dd++) {
            float w = sW[dd][ol];
#pragma unroll
            for (int r = 0; r < 8; r++)
                acc[r] = fmaf(sA[ig + r * 4][dd], w, acc[r]);
        }
    }
    float bv = bias[o0 + ol];
#pragma unroll
    for (int r = 0; r < 8; r++)
        C[(size_t)(i0 + ig + r * 4) * ldc + o0 + ol] = acc[r] + bv;
}

// ---------------- kernel 3: scatter projections + transform points -----------
__global__ void scatter_kernel(const float* __restrict__ T)
{
    int i = blockIdx.x;
    const float* raw = g_raw + (size_t)i * DPROJ;
    const float* Ti  = T + (size_t)i * 16;

    for (int t = threadIdx.x; t < 768; t += blockDim.x) {
        if (t < 576) {
            int kind = t / 192, d = t % 192;
            int h = d / 16, c = d % 16;
            float v = raw[kind * 192 + d];
            if (kind == 0) v *= 0.25f;  // q * 1/sqrt(C)
            float* dst = (kind == 0) ? g_q : ((kind == 1) ? g_k : g_v);
            dst[(h * N_RESV + i) * CHV + c] = v;
        } else {
            int t2 = t - 576;
            int kind, hp, P, base;
            if      (t2 < 48)  { kind = 0; hp = t2;       P = NQPV; base = 576; }
            else if (t2 < 96)  { kind = 1; hp = t2 - 48;  P = NQPV; base = 720; }
            else               { kind = 2; hp = t2 - 96;  P = NPVV; base = 864; }
            int HP = NHV * P;
            float px = raw[base + 0 * HP + hp];
            float py = raw[base + 1 * HP + hp];
            float pz = raw[base + 2 * HP + hp];
            float ox = Ti[0] * px + Ti[1] * py + Ti[2]  * pz + Ti[3];
            float oy = Ti[4] * px + Ti[5] * py + Ti[6]  * pz + Ti[7];
            float oz = Ti[8] * px + Ti[9] * py + Ti[10] * pz + Ti[11];
            float* dst = (kind == 0) ? g_tqp : ((kind == 1) ? g_tkp : g_tvp);
            float* o = dst + ((size_t)hp * N_RESV + i) * 3;
            o[0] = ox; o[1] = oy; o[2] = oz;
        }
    }
}

// ---------------- kernel 4: bias = z @ Wb + bb  (skinny GEMM) ----------------
// grid 576, block 128. Each block: 256 rows; each thread: 2 rows x 12 heads.
__global__ void bias_gemm_kernel(const float* __restrict__ z,
                                 const float* __restrict__ Wb,
                                 const float* __restrict__ bb)
{
    __shared__ float sWb[CZV * NHV];       // [c][h]
    __shared__ float sz[256][33];
    int r0 = blockIdx.x * 256;
    int t = threadIdx.x;

    for (int idx = t; idx < CZV * NHV; idx += 128) sWb[idx] = Wb[idx];

    float acc0[NHV], acc1[NHV];
#pragma unroll
    for (int h = 0; h < NHV; h++) { acc0[h] = 0.f; acc1[h] = 0.f; }

    for (int ct = 0; ct < CZV; ct += 32) {
        __syncthreads();
        for (int idx = t; idx < 2048; idx += 128) {
            int row = idx >> 3, v4 = idx & 7;
            float4 val = *(const float4*)&z[(size_t)(r0 + row) * CZV + ct + v4 * 4];
            float* dst = &sz[row][v4 * 4];
            dst[0] = val.x; dst[1] = val.y; dst[2] = val.z; dst[3] = val.w;
        }
        __syncthreads();
        const float* wbp = &sWb[ct * NHV];
#pragma unroll 8
        for (int cc = 0; cc < 32; cc++) {
            float z0 = sz[t][cc];
            float z1 = sz[t + 128][cc];
#pragma unroll
            for (int h = 0; h < NHV; h++) {
                float w = wbp[cc * NHV + h];
                acc0[h] = fmaf(z0, w, acc0[h]);
                acc1[h] = fmaf(z1, w, acc1[h]);
            }
        }
    }
#pragma unroll
    for (int h = 0; h < NHV; h++) {
        float bh = bb[h];
        g_bias[(size_t)h * NROWS + r0 + t]       = acc0[h] + bh;
        g_bias[(size_t)h * NROWS + r0 + 128 + t] = acc1[h] + bh;
    }
}

// ---------------- kernel 5: logits + softmax. grid (48, 12), block 256 -------
// 8 warps per block, warp w owns residue i = i0 + w.
__global__ void att_kernel(const float* __restrict__ head_weights)
{
    int h = blockIdx.y;
    int i0 = blockIdx.x * 8;
    __shared__ float sk [32][17];
    __shared__ float skp[32][12];
    __shared__ float sq [8][16];
    __shared__ float sqp[8][12];
    __shared__ float slog[8][N_RESV];

    int t = threadIdx.x, w = t >> 5, lane = t & 31;

    if (t < 128) {
        int iw = t / 16, c = t % 16;
        sq[iw][c] = g_q[(h * N_RESV + i0 + iw) * CHV + c];
    }
    if (t < 96) {
        int iw = t / 12, u = t % 12, p = u / 3, d = u % 3;
        sqp[iw][u] = g_tqp[((h * NQPV + p) * N_RESV + i0 + iw) * 3 + d];
    }
    float hw = head_weights[h];
    float gamma = (hw > 20.f) ? hw : log1pf(expf(hw));
    const float wc = 0.23570226039551584f;
    const float wl = 0.57735026918962576f;
    float coef = gamma * wc * 0.5f;

    const float* brow = &g_bias[(size_t)h * NROWS + (size_t)(i0 + w) * N_RESV];

    for (int j0 = 0; j0 < N_RESV; j0 += 32) {
        __syncthreads();
        for (int idx = t; idx < 32 * 16; idx += 256)
            sk[idx >> 4][idx & 15] = g_k[(h * N_RESV + j0 + (idx >> 4)) * CHV + (idx & 15)];
        for (int idx = t; idx < 32 * 12; idx += 256) {
            int j = idx / 12, u = idx % 12, p = u / 3, d = u % 3;
            skp[j][u] = g_tkp[((h * NQPV + p) * N_RESV + j0 + j) * 3 + d];
        }
        __syncthreads();
        int j = j0 + lane;
        float qk = 0.f;
#pragma unroll
        for (int c = 0; c < CHV; c++) qk = fmaf(sq[w][c], sk[lane][c], qk);
        float d2 = 0.f;
#pragma unroll
        for (int p = 0; p < NQPV; p++) {
            float dx = sqp[w][p * 3 + 0] - skp[lane][p * 3 + 0];
            float dy = sqp[w][p * 3 + 1] - skp[lane][p * 3 + 1];
            float dz = sqp[w][p * 3 + 2] - skp[lane][p * 3 + 2];
            d2 += dx * dx + dy * dy + dz * dz;
        }
        slog[w][j] = wl * (qk + brow[j] - coef * d2);
    }

    // warp-local softmax over 384 entries
    float m = -1e30f;
#pragma unroll
    for (int r = 0; r < 12; r++) m = fmaxf(m, slog[w][lane + r * 32]);
#pragma unroll
    for (int o = 16; o; o >>= 1) m = fmaxf(m, __shfl_xor_sync(0xffffffffu, m, o));
    float ssum = 0.f;
#pragma unroll
    for (int r = 0; r < 12; r++) {
        float e = expf(slog[w][lane + r * 32] - m);
        slog[w][lane + r * 32] = e;
        ssum += e;
    }
#pragma unroll
    for (int o = 16; o; o >>= 1) ssum += __shfl_xor_sync(0xffffffffu, ssum, o);
    float inv = 1.f / ssum;
    float* arow = &g_att[(size_t)h * NROWS + (size_t)(i0 + w) * N_RESV];
#pragma unroll
    for (int r = 0; r < 12; r++) arow[lane + r * 32] = slog[w][lane + r * 32] * inv;
}

// ---------------- kernel 6: per-head GEMM  att[h] @ [v|vp] -------------------
// grid (6, 12), block 256; tile 64 rows x 40 cols, 10 outputs/thread.
__global__ void att_av_kernel()
{
    int h = blockIdx.y;
    int i0 = blockIdx.x * 64;
    __shared__ float satt[64][65];
    __shared__ float sx[64][41];
    int t = threadIdx.x;
    int r  = t >> 2;
    int c0 = t & 3;
    float acc[10];
#pragma unroll
    for (int k = 0; k < 10; k++) acc[k] = 0.f;

    for (int j0 = 0; j0 < N_RESV; j0 += 64) {
        __syncthreads();
        for (int idx = t; idx < 64 * 16; idx += 256) {
            int row = idx >> 4, v4 = idx & 15;
            float4 v = *(const float4*)&g_att[((size_t)h * N_RESV + i0 + row) * N_RESV + j0 + v4 * 4];
            float* dst = &satt[row][v4 * 4];
            dst[0] = v.x; dst[1] = v.y; dst[2] = v.z; dst[3] = v.w;
        }
        for (int idx = t; idx < 64 * 40; idx += 256) {
            int j = idx / 40, col = idx % 40;
            float v;
            if (col < 16) v = g_v[(h * N_RESV + j0 + j) * CHV + col];
            else {
                int u = col - 16, p = u / 3, d = u % 3;
                v = g_tvp[((h * NPVV + p) * N_RESV + j0 + j) * 3 + d];
            }
            sx[j][col] = v;
        }
        __syncthreads();
#pragma unroll 4
        for (int jj = 0; jj < 64; jj++) {
            float a = satt[r][jj];
#pragma unroll
            for (int k = 0; k < 10; k++)
                acc[k] = fmaf(a, sx[jj][c0 + k * 4], acc[k]);
        }
    }
#pragma unroll
    for (int k = 0; k < 10; k++)
        g_av[((size_t)h * N_RESV + i0 + r) * 40 + c0 + k * 4] = acc[k];
}

// ---------------- kernel 7: pairwise GEMM + finalize -> concat row -----------
// block per i, 384 threads (12 heads x 32 float4-cols)
__global__ void out_kernel(const float* __restrict__ z,
                           const float* __restrict__ T)
{
    int i = blockIdx.x;
    __shared__ float att[NHV][N_RESV];   // 18 KB
    __shared__ float ztile[32][132];     // 16.9 KB (float4-aligned pitch)
    int t = threadIdx.x;

    for (int idx = t; idx < NHV * N_RESV; idx += 384) {
        int h = idx / N_RESV, j = idx % N_RESV;
        att[h][j] = g_att[((size_t)h * N_RESV + i) * N_RESV + j];
    }

    int h  = t >> 5;
    int c4 = t & 31;
    float4 acc = make_float4(0.f, 0.f, 0.f, 0.f);

    for (int j0 = 0; j0 < N_RESV; j0 += 32) {
        __syncthreads();
        for (int idx = t; idx < 32 * 32; idx += 384) {
            int row = idx >> 5, v4 = idx & 31;
            float4 v = *(const float4*)&z[((size_t)i * N_RESV + j0 + row) * CZV + v4 * 4];
            *(float4*)&ztile[row][v4 * 4] = v;
        }
        __syncthreads();
#pragma unroll 4
        for (int jj = 0; jj < 32; jj++) {
            float a = att[h][j0 + jj];
            float4 zv = *(const float4*)&ztile[jj][c4 * 4];
            acc.x = fmaf(a, zv.x, acc.x);
            acc.y = fmaf(a, zv.y, acc.y);
            acc.z = fmaf(a, zv.z, acc.z);
            acc.w = fmaf(a, zv.w, acc.w);
        }
    }
    float* crow = g_concat + (size_t)i * DCAT;
    *(float4*)&crow[576 + h * CZV + c4 * 4] = acc;

    // v_out copy
    if (t < 192) {
        int hh = t / 16, cc = t % 16;
        crow[hh * 16 + cc] = g_av[((size_t)hh * N_RESV + i) * 40 + cc];
    }
    // inverse transform + norm
    const float* Ti = T + (size_t)i * 16;
    if (t < 96) {
        int hh = t / 8, p = t % 8;
        const float* av = &g_av[((size_t)hh * N_RESV + i) * 40 + 16 + p * 3];
        float px = av[0] - Ti[3];
        float py = av[1] - Ti[7];
        float pz = av[2] - Ti[11];
        float ox = Ti[0] * px + Ti[4] * py + Ti[8]  * pz;
        float oy = Ti[1] * px + Ti[5] * py + Ti[9]  * pz;
        float oz = Ti[2] * px + Ti[6] * py + Ti[10] * pz;
        crow[192 +   0 + hh * 8 + p] = ox;
        crow[192 +  96 + hh * 8 + p] = oy;
        crow[192 + 192 + hh * 8 + p] = oz;
        crow[480 + hh * 8 + p] = sqrtf(ox * ox + oy * oy + oz * oz);
    }
}

// ---------------- launch ------------------------------------------------------
extern "C" void kernel_launch(void* const* d_in, const int* in_sizes, int n_in,
                              void* d_out, int out_size)
{
    const float* s   = (const float*)d_in[0];
    const float* z   = (const float*)d_in[1];
    const float* T   = (const float*)d_in[2];
    const float* Wq  = (const float*)d_in[3];
    const float* bq  = (const float*)d_in[4];
    const float* Wk  = (const float*)d_in[5];
    const float* bk  = (const float*)d_in[6];
    const float* Wv  = (const float*)d_in[7];
    const float* bv  = (const float*)d_in[8];
    const float* Wqp = (const float*)d_in[9];
    const float* bqp = (const float*)d_in[10];
    const float* Wkp = (const float*)d_in[11];
    const float* bkp = (const float*)d_in[12];
    const float* Wvp = (const float*)d_in[13];
    const float* bvp = (const float*)d_in[14];
    const float* Wb  = (const float*)d_in[15];
    const float* bb  = (const float*)d_in[16];
    const float* Wo  = (const float*)d_in[17];
    const float* bo  = (const float*)d_in[18];
    const float* hwt = (const float*)d_in[19];

    float* out = (float*)d_out;

    float* raw_p;    cudaGetSymbolAddress((void**)&raw_p,    g_raw);
    float* wcat_p;   cudaGetSymbolAddress((void**)&wcat_p,   g_Wcat);
    float* bcat_p;   cudaGetSymbolAddress((void**)&bcat_p,   g_bcat);
    float* concat_p; cudaGetSymbolAddress((void**)&concat_p, g_concat);

    build_wcat_kernel<<<432, 256>>>(Wq, bq, Wk, bk, Wv, bv,
                                    Wqp, bqp, Wkp, bkp, Wvp, bvp);

    gemm_tiled_kernel<<<dim3(N_RESV / 32, DPROJ / 64), 256>>>(
        s, CSV, wcat_p, DPROJ, bcat_p, raw_p, DPROJ, CSV);

    scatter_kernel<<<N_RESV, 256>>>(T);

    bias_gemm_kernel<<<NROWS / 256, 128>>>(z, Wb, bb);

    att_kernel<<<dim3(48, NHV), 256>>>(hwt);

    att_av_kernel<<<dim3(6, NHV), 256>>>();

    out_kernel<<<N_RESV, 384>>>(z, T);

    gemm_tiled_kernel<<<dim3(N_RESV / 32, N_RESV / 64), 256>>>(
        concat_p, DCAT, Wo, CSV, bo, out, CSV, DCAT);
}

// round 3
// speedup vs baseline: 2.4594x; 1.6379x over previous
#include <cuda_runtime.h>
#include <math.h>

#define N_RESV 384
#define CSV    384
#define CZV    128
#define NHV    12
#define CHV    16
#define NQPV   4
#define NPVV   8
#define DPROJ  1152
#define DCAT   2112
#define NROWS  (N_RESV * N_RESV)
#define SPLITK 4
#define KSLICE (DCAT / SPLITK)   // 528

// ---------------- scratch ----------------------------------------------------
__device__ float g_Wcat[CSV * DPROJ];
__device__ float g_bcat[DPROJ];
__device__ float g_raw [N_RESV * DPROJ];
__device__ float g_q [NHV * N_RESV * CHV];
__device__ float g_k [NHV * N_RESV * CHV];
__device__ float g_v [NHV * N_RESV * CHV];
__device__ float g_tqp[NHV * NQPV * N_RESV * 3];
__device__ float g_tkp[NHV * NQPV * N_RESV * 3];
__device__ float g_tvp[NHV * NPVV * N_RESV * 3];
__device__ float g_bias[NHV * NROWS];
__device__ float g_att [NHV * NROWS];
__device__ float g_av  [NHV * N_RESV * 40];
__device__ float g_concat[N_RESV * DCAT];
__device__ float g_part[SPLITK * N_RESV * N_RESV];

// ---------------- kernel 1: build concatenated projection weights ------------
__global__ void build_wcat_kernel(
    const float* Wq, const float* bq, const float* Wk, const float* bk,
    const float* Wv, const float* bv, const float* Wqp, const float* bqp,
    const float* Wkp, const float* bkp, const float* Wvp, const float* bvp)
{
    int idx = blockIdx.x * blockDim.x + threadIdx.x;
    int stride = gridDim.x * blockDim.x;
    const int total = CSV * DPROJ;
    for (int t = idx; t < total; t += stride) {
        int c = t / DPROJ, d = t % DPROJ;
        float v;
        if      (d < 192)  v = Wq [c * 192 + d];
        else if (d < 384)  v = Wk [c * 192 + (d - 192)];
        else if (d < 576)  v = Wv [c * 192 + (d - 384)];
        else if (d < 720)  v = Wqp[c * 144 + (d - 576)];
        else if (d < 864)  v = Wkp[c * 144 + (d - 720)];
        else               v = Wvp[c * 288 + (d - 864)];
        g_Wcat[t] = v;
    }
    for (int d = idx; d < DPROJ; d += stride) {
        float v;
        if      (d < 192)  v = bq [d];
        else if (d < 384)  v = bk [d - 192];
        else if (d < 576)  v = bv [d - 384];
        else if (d < 720)  v = bqp[d - 576];
        else if (d < 864)  v = bkp[d - 720];
        else               v = bvp[d - 864];
        g_bcat[d] = v;
    }
}

// ---------- register-tiled GEMM: 64x64 tile, 4x4 per thread, 256 threads ----
// C_plane[z][M,N] = A[M, k0:k0+kLen] @ W[k0:k0+kLen, N]  (k0 = z*kLen)
// If gridDim.z == 1, bias (non-null) is added.
__global__ void gemm64_kernel(const float* __restrict__ A, int lda,
                              const float* __restrict__ W, int ldw,
                              const float* __restrict__ bias,
                              float* __restrict__ C, int ldc, int kLen)
{
    __shared__ float sA[16][68];   // [k][m]
    __shared__ float sB[16][68];   // [k][n]
    int i0 = blockIdx.x * 64;
    int o0 = blockIdx.y * 64;
    int k0 = blockIdx.z * kLen;
    C += (size_t)blockIdx.z * (size_t)(gridDim.x * 64) * ldc;

    int t  = threadIdx.x;
    int tc = t & 15;     // N dir
    int tr = t >> 4;     // M dir

    // A-load mapping: 256 threads x float4 = 1024 floats = 64 rows x 16 k
    int ar = t >> 2;          // 0..63
    int ak = (t & 3) * 4;     // 0,4,8,12
    // B-load mapping: 16 k x 64 n
    int bk = t >> 4;          // 0..15
    int bn = (t & 15) * 4;

    float acc[4][4];
#pragma unroll
    for (int i = 0; i < 4; i++)
#pragma unroll
        for (int j = 0; j < 4; j++) acc[i][j] = 0.f;

    for (int kk = 0; kk < kLen; kk += 16) {
        __syncthreads();
        float4 av = *(const float4*)&A[(size_t)(i0 + ar) * lda + k0 + kk + ak];
        sA[ak + 0][ar] = av.x;
        sA[ak + 1][ar] = av.y;
        sA[ak + 2][ar] = av.z;
        sA[ak + 3][ar] = av.w;
        float4 bv = *(const float4*)&W[(size_t)(k0 + kk + bk) * ldw + o0 + bn];
        *(float4*)&sB[bk][bn] = bv;
        __syncthreads();
#pragma unroll
        for (int k = 0; k < 16; k++) {
            float4 a = *(const float4*)&sA[k][tr * 4];
            float4 b = *(const float4*)&sB[k][tc * 4];
            float aa[4] = {a.x, a.y, a.z, a.w};
            float bb4[4] = {b.x, b.y, b.z, b.w};
#pragma unroll
            for (int i = 0; i < 4; i++)
#pragma unroll
                for (int j = 0; j < 4; j++)
                    acc[i][j] = fmaf(aa[i], bb4[j], acc[i][j]);
        }
    }

#pragma unroll
    for (int i = 0; i < 4; i++) {
        float* crow = &C[(size_t)(i0 + tr * 4 + i) * ldc + o0 + tc * 4];
        float4 o;
        if (bias) {
            const float* bp = &bias[o0 + tc * 4];
            o = make_float4(acc[i][0] + bp[0], acc[i][1] + bp[1],
                            acc[i][2] + bp[2], acc[i][3] + bp[3]);
        } else {
            o = make_float4(acc[i][0], acc[i][1], acc[i][2], acc[i][3]);
        }
        *(float4*)crow = o;
    }
}

// ---------------- split-K reduce + bias --------------------------------------
__global__ void reduce_kernel(const float* __restrict__ bias,
                              float* __restrict__ out)
{
    int idx = blockIdx.x * blockDim.x + threadIdx.x;
    if (idx >= NROWS) return;
    int n = idx % N_RESV;
    float v = g_part[idx] + g_part[idx + NROWS] + g_part[idx + 2 * NROWS]
            + g_part[idx + 3 * NROWS];
    out[idx] = v + bias[n];
}

// ---------------- kernel 3: scatter projections + transform points -----------
__global__ void scatter_kernel(const float* __restrict__ T)
{
    int i = blockIdx.x;
    const float* raw = g_raw + (size_t)i * DPROJ;
    const float* Ti  = T + (size_t)i * 16;

    for (int t = threadIdx.x; t < 768; t += blockDim.x) {
        if (t < 576) {
            int kind = t / 192, d = t % 192;
            int h = d / 16, c = d % 16;
            float v = raw[kind * 192 + d];
            if (kind == 0) v *= 0.25f;
            float* dst = (kind == 0) ? g_q : ((kind == 1) ? g_k : g_v);
            dst[(h * N_RESV + i) * CHV + c] = v;
        } else {
            int t2 = t - 576;
            int kind, hp, P, base;
            if      (t2 < 48)  { kind = 0; hp = t2;       P = NQPV; base = 576; }
            else if (t2 < 96)  { kind = 1; hp = t2 - 48;  P = NQPV; base = 720; }
            else               { kind = 2; hp = t2 - 96;  P = NPVV; base = 864; }
            int HP = NHV * P;
            float px = raw[base + 0 * HP + hp];
            float py = raw[base + 1 * HP + hp];
            float pz = raw[base + 2 * HP + hp];
            float ox = Ti[0] * px + Ti[1] * py + Ti[2]  * pz + Ti[3];
            float oy = Ti[4] * px + Ti[5] * py + Ti[6]  * pz + Ti[7];
            float oz = Ti[8] * px + Ti[9] * py + Ti[10] * pz + Ti[11];
            float* dst = (kind == 0) ? g_tqp : ((kind == 1) ? g_tkp : g_tvp);
            float* o = dst + ((size_t)hp * N_RESV + i) * 3;
            o[0] = ox; o[1] = oy; o[2] = oz;
        }
    }
}

// ---------------- kernel 4: bias = z @ Wb + bb  ------------------------------
// grid 576, block 256; 256 rows/block, 1 row/thread.
__global__ void bias_gemm_kernel(const float* __restrict__ z,
                                 const float* __restrict__ Wb,
                                 const float* __restrict__ bb)
{
    __shared__ float sWb[CZV * NHV];
    __shared__ float sz[256][33];
    int r0 = blockIdx.x * 256;
    int t = threadIdx.x;

    for (int idx = t; idx < CZV * NHV; idx += 256) sWb[idx] = Wb[idx];

    float acc[NHV];
#pragma unroll
    for (int h = 0; h < NHV; h++) acc[h] = 0.f;

    for (int ct = 0; ct < CZV; ct += 32) {
        __syncthreads();
        for (int idx = t; idx < 2048; idx += 256) {
            int row = idx >> 3, v4 = idx & 7;
            float4 val = *(const float4*)&z[(size_t)(r0 + row) * CZV + ct + v4 * 4];
            float* dst = &sz[row][v4 * 4];
            dst[0] = val.x; dst[1] = val.y; dst[2] = val.z; dst[3] = val.w;
        }
        __syncthreads();
        const float* wbp = &sWb[ct * NHV];
#pragma unroll 8
        for (int cc = 0; cc < 32; cc++) {
            float z0 = sz[t][cc];
#pragma unroll
            for (int h = 0; h < NHV; h++)
                acc[h] = fmaf(z0, wbp[cc * NHV + h], acc[h]);
        }
    }
#pragma unroll
    for (int h = 0; h < NHV; h++)
        g_bias[(size_t)h * NROWS + r0 + t] = acc[h] + bb[h];
}

// ---------------- kernel 5: logits + softmax. grid (48, 12), block 256 -------
__global__ void att_kernel(const float* __restrict__ head_weights)
{
    int h = blockIdx.y;
    int i0 = blockIdx.x * 8;
    __shared__ float sk [32][17];
    __shared__ float skp[32][12];
    __shared__ float sq [8][16];
    __shared__ float sqp[8][12];
    __shared__ float slog[8][N_RESV];

    int t = threadIdx.x, w = t >> 5, lane = t & 31;

    if (t < 128) {
        int iw = t / 16, c = t % 16;
        sq[iw][c] = g_q[(h * N_RESV + i0 + iw) * CHV + c];
    }
    if (t < 96) {
        int iw = t / 12, u = t % 12, p = u / 3, d = u % 3;
        sqp[iw][u] = g_tqp[((h * NQPV + p) * N_RESV + i0 + iw) * 3 + d];
    }
    float hw = head_weights[h];
    float gamma = (hw > 20.f) ? hw : log1pf(expf(hw));
    const float wc = 0.23570226039551584f;
    const float wl = 0.57735026918962576f;
    float coef = gamma * wc * 0.5f;

    const float* brow = &g_bias[(size_t)h * NROWS + (size_t)(i0 + w) * N_RESV];

    for (int j0 = 0; j0 < N_RESV; j0 += 32) {
        __syncthreads();
        for (int idx = t; idx < 32 * 16; idx += 256)
            sk[idx >> 4][idx & 15] = g_k[(h * N_RESV + j0 + (idx >> 4)) * CHV + (idx & 15)];
        for (int idx = t; idx < 32 * 12; idx += 256) {
            int j = idx / 12, u = idx % 12, p = u / 3, d = u % 3;
            skp[j][u] = g_tkp[((h * NQPV + p) * N_RESV + j0 + j) * 3 + d];
        }
        __syncthreads();
        int j = j0 + lane;
        float qk = 0.f;
#pragma unroll
        for (int c = 0; c < CHV; c++) qk = fmaf(sq[w][c], sk[lane][c], qk);
        float d2 = 0.f;
#pragma unroll
        for (int p = 0; p < NQPV; p++) {
            float dx = sqp[w][p * 3 + 0] - skp[lane][p * 3 + 0];
            float dy = sqp[w][p * 3 + 1] - skp[lane][p * 3 + 1];
            float dz = sqp[w][p * 3 + 2] - skp[lane][p * 3 + 2];
            d2 += dx * dx + dy * dy + dz * dz;
        }
        slog[w][j] = wl * (qk + brow[j] - coef * d2);
    }

    float m = -1e30f;
#pragma unroll
    for (int r = 0; r < 12; r++) m = fmaxf(m, slog[w][lane + r * 32]);
#pragma unroll
    for (int o = 16; o; o >>= 1) m = fmaxf(m, __shfl_xor_sync(0xffffffffu, m, o));
    float ssum = 0.f;
#pragma unroll
    for (int r = 0; r < 12; r++) {
        float e = expf(slog[w][lane + r * 32] - m);
        slog[w][lane + r * 32] = e;
        ssum += e;
    }
#pragma unroll
    for (int o = 16; o; o >>= 1) ssum += __shfl_xor_sync(0xffffffffu, ssum, o);
    float inv = 1.f / ssum;
    float* arow = &g_att[(size_t)h * NROWS + (size_t)(i0 + w) * N_RESV];
#pragma unroll
    for (int r = 0; r < 12; r++) arow[lane + r * 32] = slog[w][lane + r * 32] * inv;
}

// ---------------- kernel 6: per-head GEMM  att[h] @ [v|vp] -------------------
__global__ void att_av_kernel()
{
    int h = blockIdx.y;
    int i0 = blockIdx.x * 64;
    __shared__ float satt[64][65];
    __shared__ float sx[64][41];
    int t = threadIdx.x;
    int r  = t >> 2;
    int c0 = t & 3;
    float acc[10];
#pragma unroll
    for (int k = 0; k < 10; k++) acc[k] = 0.f;

    for (int j0 = 0; j0 < N_RESV; j0 += 64) {
        __syncthreads();
        for (int idx = t; idx < 64 * 16; idx += 256) {
            int row = idx >> 4, v4 = idx & 15;
            float4 v = *(const float4*)&g_att[((size_t)h * N_RESV + i0 + row) * N_RESV + j0 + v4 * 4];
            float* dst = &satt[row][v4 * 4];
            dst[0] = v.x; dst[1] = v.y; dst[2] = v.z; dst[3] = v.w;
        }
        for (int idx = t; idx < 64 * 40; idx += 256) {
            int j = idx / 40, col = idx % 40;
            float v;
            if (col < 16) v = g_v[(h * N_RESV + j0 + j) * CHV + col];
            else {
                int u = col - 16, p = u / 3, d = u % 3;
                v = g_tvp[((h * NPVV + p) * N_RESV + j0 + j) * 3 + d];
            }
            sx[j][col] = v;
        }
        __syncthreads();
#pragma unroll 4
        for (int jj = 0; jj < 64; jj++) {
            float a = satt[r][jj];
#pragma unroll
            for (int k = 0; k < 10; k++)
                acc[k] = fmaf(a, sx[jj][c0 + k * 4], acc[k]);
        }
    }
#pragma unroll
    for (int k = 0; k < 10; k++)
        g_av[((size_t)h * N_RESV + i0 + r) * 40 + c0 + k * 4] = acc[k];
}

// ---------------- kernel 7: pairwise GEMM + finalize -> concat row -----------
__global__ void out_kernel(const float* __restrict__ z,
                           const float* __restrict__ T)
{
    int i = blockIdx.x;
    __shared__ float att[NHV][N_RESV];
    __shared__ float ztile[32][132];
    int t = threadIdx.x;

    for (int idx = t; idx < NHV * N_RESV; idx += 384) {
        int h = idx / N_RESV, j = idx % N_RESV;
        att[h][j] = g_att[((size_t)h * N_RESV + i) * N_RESV + j];
    }

    int h  = t >> 5;
    int c4 = t & 31;
    float4 acc = make_float4(0.f, 0.f, 0.f, 0.f);

    for (int j0 = 0; j0 < N_RESV; j0 += 32) {
        __syncthreads();
        for (int idx = t; idx < 32 * 32; idx += 384) {
            int row = idx >> 5, v4 = idx & 31;
            float4 v = *(const float4*)&z[((size_t)i * N_RESV + j0 + row) * CZV + v4 * 4];
            *(float4*)&ztile[row][v4 * 4] = v;
        }
        __syncthreads();
#pragma unroll 4
        for (int jj = 0; jj < 32; jj++) {
            float a = att[h][j0 + jj];
            float4 zv = *(const float4*)&ztile[jj][c4 * 4];
            acc.x = fmaf(a, zv.x, acc.x);
            acc.y = fmaf(a, zv.y, acc.y);
            acc.z = fmaf(a, zv.z, acc.z);
            acc.w = fmaf(a, zv.w, acc.w);
        }
    }
    float* crow = g_concat + (size_t)i * DCAT;
    *(float4*)&crow[576 + h * CZV + c4 * 4] = acc;

    if (t < 192) {
        int hh = t / 16, cc = t % 16;
        crow[hh * 16 + cc] = g_av[((size_t)hh * N_RESV + i) * 40 + cc];
    }
    const float* Ti = T + (size_t)i * 16;
    if (t < 96) {
        int hh = t / 8, p = t % 8;
        const float* av = &g_av[((size_t)hh * N_RESV + i) * 40 + 16 + p * 3];
        float px = av[0] - Ti[3];
        float py = av[1] - Ti[7];
        float pz = av[2] - Ti[11];
        float ox = Ti[0] * px + Ti[4] * py + Ti[8]  * pz;
        float oy = Ti[1] * px + Ti[5] * py + Ti[9]  * pz;
        float oz = Ti[2] * px + Ti[6] * py + Ti[10] * pz;
        crow[192 +   0 + hh * 8 + p] = ox;
        crow[192 +  96 + hh * 8 + p] = oy;
        crow[192 + 192 + hh * 8 + p] = oz;
        crow[480 + hh * 8 + p] = sqrtf(ox * ox + oy * oy + oz * oz);
    }
}

// ---------------- launch ------------------------------------------------------
extern "C" void kernel_launch(void* const* d_in, const int* in_sizes, int n_in,
                              void* d_out, int out_size)
{
    const float* s   = (const float*)d_in[0];
    const float* z   = (const float*)d_in[1];
    const float* T   = (const float*)d_in[2];
    const float* Wq  = (const float*)d_in[3];
    const float* bq  = (const float*)d_in[4];
    const float* Wk  = (const float*)d_in[5];
    const float* bk  = (const float*)d_in[6];
    const float* Wv  = (const float*)d_in[7];
    const float* bv  = (const float*)d_in[8];
    const float* Wqp = (const float*)d_in[9];
    const float* bqp = (const float*)d_in[10];
    const float* Wkp = (const float*)d_in[11];
    const float* bkp = (const float*)d_in[12];
    const float* Wvp = (const float*)d_in[13];
    const float* bvp = (const float*)d_in[14];
    const float* Wb  = (const float*)d_in[15];
    const float* bb  = (const float*)d_in[16];
    const float* Wo  = (const float*)d_in[17];
    const float* bo  = (const float*)d_in[18];
    const float* hwt = (const float*)d_in[19];

    float* out = (float*)d_out;

    float* raw_p;    cudaGetSymbolAddress((void**)&raw_p,    g_raw);
    float* wcat_p;   cudaGetSymbolAddress((void**)&wcat_p,   g_Wcat);
    float* bcat_p;   cudaGetSymbolAddress((void**)&bcat_p,   g_bcat);
    float* concat_p; cudaGetSymbolAddress((void**)&concat_p, g_concat);
    float* part_p;   cudaGetSymbolAddress((void**)&part_p,   g_part);

    build_wcat_kernel<<<432, 256>>>(Wq, bq, Wk, bk, Wv, bv,
                                    Wqp, bqp, Wkp, bkp, Wvp, bvp);

    // projections: (384 x 384) @ (384 x 1152), full-K, bias fused
    gemm64_kernel<<<dim3(N_RESV / 64, DPROJ / 64, 1), 256>>>(
        s, CSV, wcat_p, DPROJ, bcat_p, raw_p, DPROJ, CSV);

    scatter_kernel<<<N_RESV, 256>>>(T);

    bias_gemm_kernel<<<NROWS / 256, 256>>>(z, Wb, bb);

    att_kernel<<<dim3(48, NHV), 256>>>(hwt);

    att_av_kernel<<<dim3(6, NHV), 256>>>();

    out_kernel<<<N_RESV, 384>>>(z, T);

    // final: (384 x 2112) @ (2112 x 384), split-K=4 partials then reduce
    gemm64_kernel<<<dim3(N_RESV / 64, N_RESV / 64, SPLITK), 256>>>(
        concat_p, DCAT, Wo, CSV, nullptr, part_p, CSV, KSLICE);

    reduce_kernel<<<(NROWS + 255) / 256, 256>>>(bo, out);
}